// round 1
// baseline (speedup 1.0000x reference)
#include <cuda_runtime.h>
#include <cstdint>

#define N_NODES   50000
#define N_EDGES   800000
#define IN_FEATS  256
#define OUT_FEATS 64

// Scratch for hw = (h @ W) * norm   [N_NODES x OUT_FEATS], 12.8 MB (L2-resident)
__device__ float g_hw[N_NODES * OUT_FEATS];

// ---------------------------------------------------------------------------
// Kernel 1: zero d_out (it is poisoned to 0xAA before timing)
// ---------------------------------------------------------------------------
__global__ void zero_kernel(float4* __restrict__ out) {
    int gid = blockIdx.x * blockDim.x + threadIdx.x;   // 800000 float4s
    if (gid < N_NODES * OUT_FEATS / 4)
        out[gid] = make_float4(0.f, 0.f, 0.f, 0.f);
}

// ---------------------------------------------------------------------------
// Kernel 2: hw[row][col] = (sum_k h[row][k] * W[k][col]) * norm[row]
// Block tile 64 rows x 64 cols, 256 threads, 4x4 register micro-tile,
// K chunked by 64 through shared memory.
// ---------------------------------------------------------------------------
__global__ __launch_bounds__(256)
void gemm_kernel(const float* __restrict__ h,
                 const float* __restrict__ norm,
                 const float* __restrict__ W) {
    __shared__ float shH[64][65];   // [row][k], pad 65 to break bank conflicts
    __shared__ float shW[64][64];   // [k][col], row stride 256B (16B aligned)

    const int tx = threadIdx.x & 15;   // col group (4 cols each)
    const int ty = threadIdx.x >> 4;   // row group (4 rows each)
    const int rowBase = blockIdx.x * 64;

    float acc[4][4];
    #pragma unroll
    for (int r = 0; r < 4; r++)
        #pragma unroll
        for (int c = 0; c < 4; c++) acc[r][c] = 0.f;

    for (int kk = 0; kk < IN_FEATS; kk += 64) {
        // Load W chunk: W[kk..kk+63][0..63] = 4096 contiguous floats
        {
            const float4* wsrc = reinterpret_cast<const float4*>(W + (size_t)kk * OUT_FEATS);
            float4* wdst = reinterpret_cast<float4*>(&shW[0][0]);
            #pragma unroll
            for (int i = threadIdx.x; i < 1024; i += 256) wdst[i] = wsrc[i];
        }
        // Load H chunk: rows rowBase..rowBase+63, k = kk..kk+63
        #pragma unroll
        for (int i = threadIdx.x; i < 1024; i += 256) {
            int r  = i >> 4;       // 0..63
            int k4 = i & 15;       // 0..15 (float4 index)
            int row = rowBase + r;
            float4 v = make_float4(0.f, 0.f, 0.f, 0.f);
            if (row < N_NODES)
                v = *reinterpret_cast<const float4*>(h + (size_t)row * IN_FEATS + kk + k4 * 4);
            shH[r][k4 * 4 + 0] = v.x;
            shH[r][k4 * 4 + 1] = v.y;
            shH[r][k4 * 4 + 2] = v.z;
            shH[r][k4 * 4 + 3] = v.w;
        }
        __syncthreads();

        #pragma unroll 16
        for (int k = 0; k < 64; k++) {
            float a0 = shH[ty * 4 + 0][k];
            float a1 = shH[ty * 4 + 1][k];
            float a2 = shH[ty * 4 + 2][k];
            float a3 = shH[ty * 4 + 3][k];
            float4 b = *reinterpret_cast<const float4*>(&shW[k][tx * 4]);
            acc[0][0] += a0 * b.x; acc[0][1] += a0 * b.y; acc[0][2] += a0 * b.z; acc[0][3] += a0 * b.w;
            acc[1][0] += a1 * b.x; acc[1][1] += a1 * b.y; acc[1][2] += a1 * b.z; acc[1][3] += a1 * b.w;
            acc[2][0] += a2 * b.x; acc[2][1] += a2 * b.y; acc[2][2] += a2 * b.z; acc[2][3] += a2 * b.w;
            acc[3][0] += a3 * b.x; acc[3][1] += a3 * b.y; acc[3][2] += a3 * b.z; acc[3][3] += a3 * b.w;
        }
        __syncthreads();
    }

    #pragma unroll
    for (int r = 0; r < 4; r++) {
        int row = rowBase + ty * 4 + r;
        if (row < N_NODES) {
            float nv = norm[row];
            float4 o = make_float4(acc[r][0] * nv, acc[r][1] * nv,
                                   acc[r][2] * nv, acc[r][3] * nv);
            *reinterpret_cast<float4*>(g_hw + (size_t)row * OUT_FEATS + tx * 4) = o;
        }
    }
}

// ---------------------------------------------------------------------------
// Kernel 3: scatter-add.  16 threads per edge, each handles one float4.
// Vector reduction (no return) to L2-resident destination.
// ---------------------------------------------------------------------------
__global__ __launch_bounds__(256)
void scatter_kernel(const int* __restrict__ src,
                    const int* __restrict__ dst,
                    float* __restrict__ out) {
    int gid = blockIdx.x * blockDim.x + threadIdx.x;  // 12.8M threads exactly
    int e = gid >> 4;
    int c = gid & 15;
    if (e < N_EDGES) {
        int s = __ldg(src + e);
        int d = __ldg(dst + e);
        float4 v = *reinterpret_cast<const float4*>(g_hw + (size_t)s * OUT_FEATS + c * 4);
        float* p = out + (size_t)d * OUT_FEATS + c * 4;
        asm volatile("red.global.add.v4.f32 [%0], {%1, %2, %3, %4};"
                     :: "l"(p), "f"(v.x), "f"(v.y), "f"(v.z), "f"(v.w)
                     : "memory");
    }
}

// ---------------------------------------------------------------------------
// Kernel 4: out = relu(out * norm + bias)
// ---------------------------------------------------------------------------
__global__ __launch_bounds__(256)
void epilogue_kernel(const float* __restrict__ norm,
                     const float* __restrict__ bias,
                     float* __restrict__ out) {
    int gid = blockIdx.x * blockDim.x + threadIdx.x;  // 800000 float4s
    if (gid >= N_NODES * OUT_FEATS / 4) return;
    int v = gid >> 4;
    int c = gid & 15;
    float4 o = *reinterpret_cast<float4*>(out + (size_t)gid * 4);
    float nv = norm[v];
    float4 b = *reinterpret_cast<const float4*>(bias + c * 4);
    o.x = fmaxf(fmaf(o.x, nv, b.x), 0.f);
    o.y = fmaxf(fmaf(o.y, nv, b.y), 0.f);
    o.z = fmaxf(fmaf(o.z, nv, b.z), 0.f);
    o.w = fmaxf(fmaf(o.w, nv, b.w), 0.f);
    *reinterpret_cast<float4*>(out + (size_t)gid * 4) = o;
}

// ---------------------------------------------------------------------------
// Launch
// ---------------------------------------------------------------------------
extern "C" void kernel_launch(void* const* d_in, const int* in_sizes, int n_in,
                              void* d_out, int out_size) {
    const float* h      = (const float*)d_in[0];   // [50000, 256]
    const float* norm   = (const float*)d_in[1];   // [50000, 1]
    const float* weight = (const float*)d_in[2];   // [256, 64]
    const float* bias   = (const float*)d_in[3];   // [64]
    const int*   src    = (const int*)d_in[4];     // [800000]
    const int*   dst    = (const int*)d_in[5];     // [800000]
    float* out = (float*)d_out;                    // [50000, 64]

    // 1) zero the aggregation buffer (d_out is poisoned)
    zero_kernel<<<(N_NODES * OUT_FEATS / 4 + 255) / 256, 256>>>((float4*)out);

    // 2) hw = (h @ W) * norm
    gemm_kernel<<<(N_NODES + 63) / 64, 256>>>(h, norm, weight);

    // 3) out[v] += hw[src[e]] for each edge (v = dst[e])
    int scatter_threads = N_EDGES * 16;
    scatter_kernel<<<(scatter_threads + 255) / 256, 256>>>(src, dst, out);

    // 4) out = relu(out * norm + bias)
    epilogue_kernel<<<(N_NODES * OUT_FEATS / 4 + 255) / 256, 256>>>(norm, bias, out);
}

// round 2
// speedup vs baseline: 1.2815x; 1.2815x over previous
#include <cuda_runtime.h>
#include <cstdint>

#define N_NODES   50000
#define N_EDGES   800000
#define IN_FEATS  256
#define OUT_FEATS 64

// Scratch for hw = (h @ W) * norm   [N_NODES x OUT_FEATS], 12.8 MB (L2-resident)
__device__ float g_hw[N_NODES * OUT_FEATS];

// ---------------------------------------------------------------------------
// Kernel 1: zero d_out (it is poisoned to 0xAA before timing)
// ---------------------------------------------------------------------------
__global__ void zero_kernel(float4* __restrict__ out) {
    int gid = blockIdx.x * blockDim.x + threadIdx.x;   // 800000 float4s
    if (gid < N_NODES * OUT_FEATS / 4)
        out[gid] = make_float4(0.f, 0.f, 0.f, 0.f);
}

// ---------------------------------------------------------------------------
// Kernel 2: hw = (h @ W) * norm   via tf32 mma.sync (m16n8k8)
// Block: 128 threads = 4 warps. Tile: 64 rows x 64 cols, K chunked by 64.
// Each warp owns 16 rows; 8 n-tiles of width 8; acc = 32 fp32 regs.
// shA stride 68 -> A-frag LDS conflict-free; shB stride 72 -> B-frag conflict-free.
// ---------------------------------------------------------------------------
#define PAD_A 68
#define PAD_B 72

__device__ __forceinline__ uint32_t f2tf32(float f) {
    uint32_t u;
    asm("cvt.rna.tf32.f32 %0, %1;" : "=r"(u) : "f"(f));
    return u;
}

__global__ __launch_bounds__(128)
void gemm_tf32_kernel(const float* __restrict__ h,
                      const float* __restrict__ norm,
                      const float* __restrict__ W) {
    __shared__ uint32_t shA[64 * PAD_A];
    __shared__ uint32_t shB[64 * PAD_B];

    const int tid  = threadIdx.x;
    const int warp = tid >> 5;
    const int lane = tid & 31;
    const int g    = lane >> 2;   // 0..7
    const int tg   = lane & 3;    // 0..3
    const int rowBase = blockIdx.x * 64;

    float acc[8][4];
    #pragma unroll
    for (int t = 0; t < 8; t++)
        #pragma unroll
        for (int i = 0; i < 4; i++) acc[t][i] = 0.f;

    for (int kk = 0; kk < IN_FEATS; kk += 64) {
        // Load A chunk: rows rowBase..+63, k = kk..kk+63, converted to tf32 bits
        #pragma unroll
        for (int i = tid; i < 1024; i += 128) {
            int r  = i >> 4;      // 0..63
            int k4 = i & 15;      // float4 index
            int row = rowBase + r;
            float4 v = make_float4(0.f, 0.f, 0.f, 0.f);
            if (row < N_NODES)
                v = *reinterpret_cast<const float4*>(h + (size_t)row * IN_FEATS + kk + k4 * 4);
            uint4 u;
            u.x = f2tf32(v.x); u.y = f2tf32(v.y); u.z = f2tf32(v.z); u.w = f2tf32(v.w);
            *reinterpret_cast<uint4*>(&shA[r * PAD_A + k4 * 4]) = u;
        }
        // Load B chunk: W[kk..kk+63][0..63]
        #pragma unroll
        for (int i = tid; i < 1024; i += 128) {
            int r  = i >> 4;      // k row 0..63
            int k4 = i & 15;      // col float4 index
            float4 v = *reinterpret_cast<const float4*>(W + (size_t)(kk + r) * OUT_FEATS + k4 * 4);
            uint4 u;
            u.x = f2tf32(v.x); u.y = f2tf32(v.y); u.z = f2tf32(v.z); u.w = f2tf32(v.w);
            *reinterpret_cast<uint4*>(&shB[r * PAD_B + k4 * 4]) = u;
        }
        __syncthreads();

        const int ar = warp * 16;
        #pragma unroll
        for (int k8 = 0; k8 < 64; k8 += 8) {
            uint32_t a0 = shA[(ar + g    ) * PAD_A + k8 + tg    ];
            uint32_t a1 = shA[(ar + g + 8) * PAD_A + k8 + tg    ];
            uint32_t a2 = shA[(ar + g    ) * PAD_A + k8 + tg + 4];
            uint32_t a3 = shA[(ar + g + 8) * PAD_A + k8 + tg + 4];
            #pragma unroll
            for (int t = 0; t < 8; t++) {
                uint32_t b0 = shB[(k8 + tg    ) * PAD_B + t * 8 + g];
                uint32_t b1 = shB[(k8 + tg + 4) * PAD_B + t * 8 + g];
                asm volatile(
                    "mma.sync.aligned.m16n8k8.row.col.f32.tf32.tf32.f32 "
                    "{%0,%1,%2,%3}, {%4,%5,%6,%7}, {%8,%9}, {%0,%1,%2,%3};"
                    : "+f"(acc[t][0]), "+f"(acc[t][1]), "+f"(acc[t][2]), "+f"(acc[t][3])
                    : "r"(a0), "r"(a1), "r"(a2), "r"(a3), "r"(b0), "r"(b1));
            }
        }
        __syncthreads();
    }

    // Store with pre-aggregation norm scale.
    // C frag: c0=C[g][2tg], c1=C[g][2tg+1], c2=C[g+8][2tg], c3=C[g+8][2tg+1]
    int r0 = rowBase + warp * 16 + g;
    int r1 = r0 + 8;
    if (r0 < N_NODES) {
        float nv = norm[r0];
        #pragma unroll
        for (int t = 0; t < 8; t++) {
            float2 o = make_float2(acc[t][0] * nv, acc[t][1] * nv);
            *reinterpret_cast<float2*>(g_hw + (size_t)r0 * OUT_FEATS + t * 8 + tg * 2) = o;
        }
    }
    if (r1 < N_NODES) {
        float nv = norm[r1];
        #pragma unroll
        for (int t = 0; t < 8; t++) {
            float2 o = make_float2(acc[t][2] * nv, acc[t][3] * nv);
            *reinterpret_cast<float2*>(g_hw + (size_t)r1 * OUT_FEATS + t * 8 + tg * 2) = o;
        }
    }
}

// ---------------------------------------------------------------------------
// Kernel 3: scatter-add.  16 threads per edge, each handles one float4.
// Vector reduction (no return) to L2-resident destination.
// ---------------------------------------------------------------------------
__global__ __launch_bounds__(256)
void scatter_kernel(const int* __restrict__ src,
                    const int* __restrict__ dst,
                    float* __restrict__ out) {
    int gid = blockIdx.x * blockDim.x + threadIdx.x;  // 12.8M threads exactly
    int e = gid >> 4;
    int c = gid & 15;
    if (e < N_EDGES) {
        int s = __ldg(src + e);
        int d = __ldg(dst + e);
        float4 v = *reinterpret_cast<const float4*>(g_hw + (size_t)s * OUT_FEATS + c * 4);
        float* p = out + (size_t)d * OUT_FEATS + c * 4;
        asm volatile("red.global.add.v4.f32 [%0], {%1, %2, %3, %4};"
                     :: "l"(p), "f"(v.x), "f"(v.y), "f"(v.z), "f"(v.w)
                     : "memory");
    }
}

// ---------------------------------------------------------------------------
// Kernel 4: out = relu(out * norm + bias)
// ---------------------------------------------------------------------------
__global__ __launch_bounds__(256)
void epilogue_kernel(const float* __restrict__ norm,
                     const float* __restrict__ bias,
                     float* __restrict__ out) {
    int gid = blockIdx.x * blockDim.x + threadIdx.x;  // 800000 float4s
    if (gid >= N_NODES * OUT_FEATS / 4) return;
    int v = gid >> 4;
    int c = gid & 15;
    float4 o = *reinterpret_cast<float4*>(out + (size_t)gid * 4);
    float nv = norm[v];
    float4 b = *reinterpret_cast<const float4*>(bias + c * 4);
    o.x = fmaxf(fmaf(o.x, nv, b.x), 0.f);
    o.y = fmaxf(fmaf(o.y, nv, b.y), 0.f);
    o.z = fmaxf(fmaf(o.z, nv, b.z), 0.f);
    o.w = fmaxf(fmaf(o.w, nv, b.w), 0.f);
    *reinterpret_cast<float4*>(out + (size_t)gid * 4) = o;
}

// ---------------------------------------------------------------------------
// Launch
// ---------------------------------------------------------------------------
extern "C" void kernel_launch(void* const* d_in, const int* in_sizes, int n_in,
                              void* d_out, int out_size) {
    const float* h      = (const float*)d_in[0];   // [50000, 256]
    const float* norm   = (const float*)d_in[1];   // [50000, 1]
    const float* weight = (const float*)d_in[2];   // [256, 64]
    const float* bias   = (const float*)d_in[3];   // [64]
    const int*   src    = (const int*)d_in[4];     // [800000]
    const int*   dst    = (const int*)d_in[5];     // [800000]
    float* out = (float*)d_out;                    // [50000, 64]

    // 1) zero the aggregation buffer (d_out is poisoned)
    zero_kernel<<<(N_NODES * OUT_FEATS / 4 + 255) / 256, 256>>>((float4*)out);

    // 2) hw = (h @ W) * norm   (tf32 tensor cores)
    gemm_tf32_kernel<<<(N_NODES + 63) / 64, 128>>>(h, norm, weight);

    // 3) out[v] += hw[src[e]] for each edge (v = dst[e])
    int scatter_threads = N_EDGES * 16;
    scatter_kernel<<<(scatter_threads + 255) / 256, 256>>>(src, dst, out);

    // 4) out = relu(out * norm + bias)
    epilogue_kernel<<<(N_NODES * OUT_FEATS / 4 + 255) / 256, 256>>>(norm, bias, out);
}